// round 5
// baseline (speedup 1.0000x reference)
#include <cuda_runtime.h>
#include <math.h>

#define T_TOK 8192
#define HDIM  1024
#define IDIM  3584
#define NEXP  8
#define MTILE 64
#define ROWCAP (2*T_TOK + NEXP*MTILE)   // 16896, every expert segment padded to 64
#define BK    32

// ---------------- scratch (static __device__, per harness rules) ----------------
__device__ float g_hbuf[(size_t)ROWCAP * IDIM];        // ~242 MB intermediate h
__device__ float g_outpair[2][T_TOK][HDIM];            // 64 MB per-slot outputs
__device__ int   g_rows[ROWCAP];                        // token | (slot<<16), -1 = pad
__device__ int   g_texp[T_TOK * 2];                     // chosen expert per (token,slot)
__device__ float g_topw[T_TOK * 2];                     // routing weight per (token,slot)
__device__ int   g_off[NEXP + 1];                       // padded segment offsets

// ---------------- f32x2 (FFMA2) helpers ----------------
__device__ __forceinline__ unsigned long long f2pack(float lo, float hi) {
    unsigned long long r;
    asm("mov.b64 %0, {%1, %2};" : "=l"(r) : "f"(lo), "f"(hi));
    return r;
}
__device__ __forceinline__ void f2unpack(unsigned long long v, float& lo, float& hi) {
    asm("mov.b64 {%0, %1}, %2;" : "=f"(lo), "=f"(hi) : "l"(v));
}
__device__ __forceinline__ unsigned long long f2fma(unsigned long long a,
                                                    unsigned long long b,
                                                    unsigned long long c) {
    unsigned long long d;
    asm("fma.rn.f32x2 %0, %1, %2, %3;" : "=l"(d) : "l"(a), "l"(b), "l"(c));
    return d;
}

// ---------------- 1) Router: logits -> softmax(fp32) -> top-2 (no renorm) ----------------
__global__ void router_kernel(const float* __restrict__ x,
                              const float* __restrict__ gw,
                              const float* __restrict__ gb) {
    __shared__ float sgw[NEXP * HDIM];  // 32 KB gate weights
    for (int i = threadIdx.x; i < NEXP * HDIM; i += blockDim.x) sgw[i] = gw[i];
    __syncthreads();

    int warp = (blockIdx.x * blockDim.x + threadIdx.x) >> 5;
    int lane = threadIdx.x & 31;
    if (warp >= T_TOK) return;

    const float* xr = x + (size_t)warp * HDIM;
    float acc[NEXP];
#pragma unroll
    for (int e = 0; e < NEXP; e++) acc[e] = 0.f;
    for (int k = lane; k < HDIM; k += 32) {
        float xv = xr[k];
#pragma unroll
        for (int e = 0; e < NEXP; e++) acc[e] = fmaf(xv, sgw[e * HDIM + k], acc[e]);
    }
#pragma unroll
    for (int e = 0; e < NEXP; e++) {
#pragma unroll
        for (int o = 16; o > 0; o >>= 1) acc[e] += __shfl_xor_sync(0xffffffffu, acc[e], o);
    }
    if (lane == 0) {
        float mx = -1e30f;
#pragma unroll
        for (int e = 0; e < NEXP; e++) { acc[e] += gb[e]; mx = fmaxf(mx, acc[e]); }
        float se = 0.f;
#pragma unroll
        for (int e = 0; e < NEXP; e++) { acc[e] = expf(acc[e] - mx); se += acc[e]; }
        float inv = 1.f / se;
        // top-2, ties -> lower index (matches lax.top_k)
        float b0 = -1.f, b1 = -1.f; int i0 = 0, i1 = 0;
#pragma unroll
        for (int e = 0; e < NEXP; e++) {
            float p = acc[e] * inv;
            if (p > b0)      { b1 = b0; i1 = i0; b0 = p; i0 = e; }
            else if (p > b1) { b1 = p;  i1 = e; }
        }
        g_texp[warp * 2 + 0] = i0;  g_texp[warp * 2 + 1] = i1;
        g_topw[warp * 2 + 0] = b0;  g_topw[warp * 2 + 1] = b1;
    }
}

// ---------------- 2) Build padded per-expert row lists (single block) ----------------
__global__ void build_lists_kernel() {
    __shared__ int cnt[NEXP], off[NEXP + 1], fill[NEXP];
    int tid = threadIdx.x;
    if (tid < NEXP) cnt[tid] = 0;
    __syncthreads();
    for (int i = tid; i < 2 * T_TOK; i += blockDim.x) atomicAdd(&cnt[g_texp[i]], 1);
    __syncthreads();
    if (tid == 0) {
        int o = 0;
        for (int e = 0; e < NEXP; e++) { off[e] = o; o += ((cnt[e] + MTILE - 1) / MTILE) * MTILE; }
        off[NEXP] = o;
    }
    __syncthreads();
    if (tid < NEXP)  fill[tid] = 0;
    if (tid <= NEXP) g_off[tid] = off[tid];
    for (int i = tid; i < ROWCAP; i += blockDim.x) g_rows[i] = -1;
    __syncthreads();
    for (int i = tid; i < 2 * T_TOK; i += blockDim.x) {
        int e = g_texp[i];
        int p = atomicAdd(&fill[e], 1);
        g_rows[off[e] + p] = (i >> 1) | ((i & 1) << 16);
    }
}

__device__ __forceinline__ int find_expert(int row0) {
    int e = 0;
#pragma unroll
    for (int q = 0; q < NEXP; q++)
        if (row0 >= g_off[q + 1]) e = q + 1;
    return e;
}

// ---------------- 3) GEMM1: h = silu(X@w1^T) * (X@w3^T), gathered rows ----------------
__global__ __launch_bounds__(256) void gemm1_kernel(const float* __restrict__ x,
                                                    const float* __restrict__ w1,
                                                    const float* __restrict__ w3) {
    __shared__ float As[BK][64];
    __shared__ float Bs1[BK][64];
    __shared__ float Bs3[BK][64];
    __shared__ int stok[64];

    int tid  = threadIdx.x;
    int row0 = blockIdx.y * MTILE;
    int n0   = blockIdx.x * 64;
    if (row0 >= g_off[NEXP]) return;
    int e = find_expert(row0);

    if (tid < 64) stok[tid] = g_rows[row0 + tid];
    __syncthreads();

    const float* B1g = w1 + (size_t)e * IDIM * HDIM;
    const float* B3g = w3 + (size_t)e * IDIM * HDIM;

    int ty = tid >> 4, tx = tid & 15;
    unsigned long long acc1[4][2], acc3[4][2];
#pragma unroll
    for (int i = 0; i < 4; i++) { acc1[i][0]=0ull; acc1[i][1]=0ull; acc3[i][0]=0ull; acc3[i][1]=0ull; }

    for (int k0 = 0; k0 < HDIM; k0 += BK) {
#pragma unroll
        for (int p = 0; p < 2; p++) {          // A tile 64x32 (gathered, transposed)
            int idx = tid + p * 256;
            int m = idx >> 3, kq = (idx & 7) << 2;
            int r = stok[m];
            float4 v = make_float4(0.f, 0.f, 0.f, 0.f);
            if (r >= 0) {
                int tok = r & 0xFFFF;
                v = *(const float4*)&x[(size_t)tok * HDIM + k0 + kq];
            }
            As[kq + 0][m] = v.x; As[kq + 1][m] = v.y; As[kq + 2][m] = v.z; As[kq + 3][m] = v.w;
        }
#pragma unroll
        for (int p = 0; p < 2; p++) {          // B1/B3 tiles 64x32 (transposed)
            int idx = tid + p * 256;
            int n = idx >> 3, kq = (idx & 7) << 2;
            float4 v1 = *(const float4*)&B1g[(size_t)(n0 + n) * HDIM + k0 + kq];
            float4 v3 = *(const float4*)&B3g[(size_t)(n0 + n) * HDIM + k0 + kq];
            Bs1[kq + 0][n] = v1.x; Bs1[kq + 1][n] = v1.y; Bs1[kq + 2][n] = v1.z; Bs1[kq + 3][n] = v1.w;
            Bs3[kq + 0][n] = v3.x; Bs3[kq + 1][n] = v3.y; Bs3[kq + 2][n] = v3.z; Bs3[kq + 3][n] = v3.w;
        }
        __syncthreads();
#pragma unroll 8
        for (int kk = 0; kk < BK; kk++) {
            float4 a4 = *(const float4*)&As[kk][ty * 4];
            unsigned long long ap0 = f2pack(a4.x, a4.x);
            unsigned long long ap1 = f2pack(a4.y, a4.y);
            unsigned long long ap2 = f2pack(a4.z, a4.z);
            unsigned long long ap3 = f2pack(a4.w, a4.w);
            ulonglong2 b1 = *(const ulonglong2*)&Bs1[kk][tx * 4];
            ulonglong2 b3 = *(const ulonglong2*)&Bs3[kk][tx * 4];
            acc1[0][0]=f2fma(ap0,b1.x,acc1[0][0]); acc1[0][1]=f2fma(ap0,b1.y,acc1[0][1]);
            acc3[0][0]=f2fma(ap0,b3.x,acc3[0][0]); acc3[0][1]=f2fma(ap0,b3.y,acc3[0][1]);
            acc1[1][0]=f2fma(ap1,b1.x,acc1[1][0]); acc1[1][1]=f2fma(ap1,b1.y,acc1[1][1]);
            acc3[1][0]=f2fma(ap1,b3.x,acc3[1][0]); acc3[1][1]=f2fma(ap1,b3.y,acc3[1][1]);
            acc1[2][0]=f2fma(ap2,b1.x,acc1[2][0]); acc1[2][1]=f2fma(ap2,b1.y,acc1[2][1]);
            acc3[2][0]=f2fma(ap2,b3.x,acc3[2][0]); acc3[2][1]=f2fma(ap2,b3.y,acc3[2][1]);
            acc1[3][0]=f2fma(ap3,b1.x,acc1[3][0]); acc1[3][1]=f2fma(ap3,b1.y,acc1[3][1]);
            acc3[3][0]=f2fma(ap3,b3.x,acc3[3][0]); acc3[3][1]=f2fma(ap3,b3.y,acc3[3][1]);
        }
        __syncthreads();
    }
    // epilogue: silu(c1) * c3  (pad rows have c1=c3=0 -> store 0, keeps hbuf clean)
#pragma unroll
    for (int i = 0; i < 4; i++) {
        float c1[4], c3[4];
        f2unpack(acc1[i][0], c1[0], c1[1]); f2unpack(acc1[i][1], c1[2], c1[3]);
        f2unpack(acc3[i][0], c3[0], c3[1]); f2unpack(acc3[i][1], c3[2], c3[3]);
        float4 hv;
        float* hp = (float*)&hv;
#pragma unroll
        for (int j = 0; j < 4; j++) {
            float s = c1[j] / (1.f + expf(-c1[j]));
            hp[j] = s * c3[j];
        }
        int m = ty * 4 + i;
        *(float4*)&g_hbuf[(size_t)(row0 + m) * IDIM + n0 + tx * 4] = hv;
    }
}

// ---------------- 4) GEMM2: out_pair[slot][tok] = w_tok * (h @ w2^T) ----------------
__global__ __launch_bounds__(256) void gemm2_kernel(const float* __restrict__ w2) {
    __shared__ float As[BK][64];
    __shared__ float Bs[BK][128];
    __shared__ int stok[64];

    int tid  = threadIdx.x;
    int row0 = blockIdx.y * MTILE;
    int n0   = blockIdx.x * 128;
    if (row0 >= g_off[NEXP]) return;
    int e = find_expert(row0);

    if (tid < 64) stok[tid] = g_rows[row0 + tid];

    const float* Bg = w2 + (size_t)e * HDIM * IDIM;
    int ty = tid >> 4, tx = tid & 15;
    unsigned long long acc[4][4];
#pragma unroll
    for (int i = 0; i < 4; i++)
#pragma unroll
        for (int j = 0; j < 4; j++) acc[i][j] = 0ull;

    for (int k0 = 0; k0 < IDIM; k0 += BK) {
#pragma unroll
        for (int p = 0; p < 2; p++) {          // A tile from hbuf (no gather)
            int idx = tid + p * 256;
            int m = idx >> 3, kq = (idx & 7) << 2;
            float4 v = *(const float4*)&g_hbuf[(size_t)(row0 + m) * IDIM + k0 + kq];
            As[kq + 0][m] = v.x; As[kq + 1][m] = v.y; As[kq + 2][m] = v.z; As[kq + 3][m] = v.w;
        }
#pragma unroll
        for (int p = 0; p < 4; p++) {          // B tile 128x32
            int idx = tid + p * 256;
            int n = idx >> 3, kq = (idx & 7) << 2;
            float4 v = *(const float4*)&Bg[(size_t)(n0 + n) * IDIM + k0 + kq];
            Bs[kq + 0][n] = v.x; Bs[kq + 1][n] = v.y; Bs[kq + 2][n] = v.z; Bs[kq + 3][n] = v.w;
        }
        __syncthreads();
#pragma unroll 8
        for (int kk = 0; kk < BK; kk++) {
            float4 a4 = *(const float4*)&As[kk][ty * 4];
            unsigned long long ap0 = f2pack(a4.x, a4.x);
            unsigned long long ap1 = f2pack(a4.y, a4.y);
            unsigned long long ap2 = f2pack(a4.z, a4.z);
            unsigned long long ap3 = f2pack(a4.w, a4.w);
            ulonglong2 bA = *(const ulonglong2*)&Bs[kk][tx * 8];
            ulonglong2 bB = *(const ulonglong2*)&Bs[kk][tx * 8 + 4];
            acc[0][0]=f2fma(ap0,bA.x,acc[0][0]); acc[0][1]=f2fma(ap0,bA.y,acc[0][1]);
            acc[0][2]=f2fma(ap0,bB.x,acc[0][2]); acc[0][3]=f2fma(ap0,bB.y,acc[0][3]);
            acc[1][0]=f2fma(ap1,bA.x,acc[1][0]); acc[1][1]=f2fma(ap1,bA.y,acc[1][1]);
            acc[1][2]=f2fma(ap1,bB.x,acc[1][2]); acc[1][3]=f2fma(ap1,bB.y,acc[1][3]);
            acc[2][0]=f2fma(ap2,bA.x,acc[2][0]); acc[2][1]=f2fma(ap2,bA.y,acc[2][1]);
            acc[2][2]=f2fma(ap2,bB.x,acc[2][2]); acc[2][3]=f2fma(ap2,bB.y,acc[2][3]);
            acc[3][0]=f2fma(ap3,bA.x,acc[3][0]); acc[3][1]=f2fma(ap3,bA.y,acc[3][1]);
            acc[3][2]=f2fma(ap3,bB.x,acc[3][2]); acc[3][3]=f2fma(ap3,bB.y,acc[3][3]);
        }
        __syncthreads();
    }
#pragma unroll
    for (int i = 0; i < 4; i++) {
        int r = stok[ty * 4 + i];
        if (r < 0) continue;                    // padding row
        int tok = r & 0xFFFF, slot = (r >> 16) & 1;
        float w = g_topw[tok * 2 + slot];
        float c[8];
        f2unpack(acc[i][0], c[0], c[1]); f2unpack(acc[i][1], c[2], c[3]);
        f2unpack(acc[i][2], c[4], c[5]); f2unpack(acc[i][3], c[6], c[7]);
        float4 o0 = make_float4(c[0]*w, c[1]*w, c[2]*w, c[3]*w);
        float4 o1 = make_float4(c[4]*w, c[5]*w, c[6]*w, c[7]*w);
        *(float4*)&g_outpair[slot][tok][n0 + tx * 8]     = o0;
        *(float4*)&g_outpair[slot][tok][n0 + tx * 8 + 4] = o1;
    }
}

// ---------------- 5) combine: out = slot0 + slot1 ----------------
__global__ void combine_kernel(float* __restrict__ out) {
    size_t i = (size_t)blockIdx.x * blockDim.x + threadIdx.x;
    const float4* p0 = (const float4*)&g_outpair[0][0][0];
    const float4* p1 = (const float4*)&g_outpair[1][0][0];
    float4 a = p0[i], b = p1[i];
    ((float4*)out)[i] = make_float4(a.x + b.x, a.y + b.y, a.z + b.z, a.w + b.w);
}

extern "C" void kernel_launch(void* const* d_in, const int* in_sizes, int n_in,
                              void* d_out, int out_size) {
    const float* x  = (const float*)d_in[0];
    const float* gw = (const float*)d_in[1];
    const float* gb = (const float*)d_in[2];
    const float* w1 = (const float*)d_in[3];
    const float* w2 = (const float*)d_in[4];
    const float* w3 = (const float*)d_in[5];
    float* out = (float*)d_out;

    router_kernel<<<T_TOK / 8, 256>>>(x, gw, gb);
    build_lists_kernel<<<1, 1024>>>();
    dim3 g1(IDIM / 64, ROWCAP / MTILE);   // (56, 264)
    gemm1_kernel<<<g1, 256>>>(x, w1, w3);
    dim3 g2(HDIM / 128, ROWCAP / MTILE);  // (8, 264)
    gemm2_kernel<<<g2, 256>>>(w2);
    combine_kernel<<<(T_TOK * HDIM / 4) / 256, 256>>>(out);
}

// round 6
// speedup vs baseline: 1.0015x; 1.0015x over previous
#include <cuda_runtime.h>
#include <math.h>

#define T_TOK 8192
#define HDIM  1024
#define IDIM  3584
#define NEXP  8
#define MTILE 64
#define ROWCAP (2*T_TOK + NEXP*MTILE)   // 16896, every expert segment padded to 64
#define BK    32

// ---------------- scratch (static __device__, per harness rules) ----------------
__device__ float g_hbuf[(size_t)ROWCAP * IDIM];        // ~242 MB intermediate h
__device__ float g_outpair[2][T_TOK][HDIM];            // 64 MB per-slot outputs
__device__ int   g_rows[ROWCAP];                        // token | (slot<<16), -1 = pad
__device__ int   g_texp[T_TOK * 2];                     // chosen expert per (token,slot)
__device__ float g_topw[T_TOK * 2];                     // routing weight per (token,slot)
__device__ int   g_off[NEXP + 1];                       // padded segment offsets

// ---------------- f32x2 (FFMA2) helpers ----------------
__device__ __forceinline__ unsigned long long f2pack(float lo, float hi) {
    unsigned long long r;
    asm("mov.b64 %0, {%1, %2};" : "=l"(r) : "f"(lo), "f"(hi));
    return r;
}
__device__ __forceinline__ void f2unpack(unsigned long long v, float& lo, float& hi) {
    asm("mov.b64 {%0, %1}, %2;" : "=f"(lo), "=f"(hi) : "l"(v));
}
__device__ __forceinline__ unsigned long long f2fma(unsigned long long a,
                                                    unsigned long long b,
                                                    unsigned long long c) {
    unsigned long long d;
    asm("fma.rn.f32x2 %0, %1, %2, %3;" : "=l"(d) : "l"(a), "l"(b), "l"(c));
    return d;
}

// ---------------- 1) Router: logits -> softmax(fp32) -> top-2 (no renorm) ----------------
__global__ void router_kernel(const float* __restrict__ x,
                              const float* __restrict__ gw,
                              const float* __restrict__ gb) {
    __shared__ float sgw[NEXP * HDIM];  // 32 KB gate weights
    for (int i = threadIdx.x; i < NEXP * HDIM; i += blockDim.x) sgw[i] = gw[i];
    __syncthreads();

    int warp = (blockIdx.x * blockDim.x + threadIdx.x) >> 5;
    int lane = threadIdx.x & 31;
    if (warp >= T_TOK) return;

    const float* xr = x + (size_t)warp * HDIM;
    float acc[NEXP];
#pragma unroll
    for (int e = 0; e < NEXP; e++) acc[e] = 0.f;
    for (int k = lane; k < HDIM; k += 32) {
        float xv = xr[k];
#pragma unroll
        for (int e = 0; e < NEXP; e++) acc[e] = fmaf(xv, sgw[e * HDIM + k], acc[e]);
    }
#pragma unroll
    for (int e = 0; e < NEXP; e++) {
#pragma unroll
        for (int o = 16; o > 0; o >>= 1) acc[e] += __shfl_xor_sync(0xffffffffu, acc[e], o);
    }
    if (lane == 0) {
        float mx = -1e30f;
#pragma unroll
        for (int e = 0; e < NEXP; e++) { acc[e] += gb[e]; mx = fmaxf(mx, acc[e]); }
        float se = 0.f;
#pragma unroll
        for (int e = 0; e < NEXP; e++) { acc[e] = expf(acc[e] - mx); se += acc[e]; }
        float inv = 1.f / se;
        // top-2, ties -> lower index (matches lax.top_k)
        float b0 = -1.f, b1 = -1.f; int i0 = 0, i1 = 0;
#pragma unroll
        for (int e = 0; e < NEXP; e++) {
            float p = acc[e] * inv;
            if (p > b0)      { b1 = b0; i1 = i0; b0 = p; i0 = e; }
            else if (p > b1) { b1 = p;  i1 = e; }
        }
        g_texp[warp * 2 + 0] = i0;  g_texp[warp * 2 + 1] = i1;
        g_topw[warp * 2 + 0] = b0;  g_topw[warp * 2 + 1] = b1;
    }
}

// ---------------- 2) Build padded per-expert row lists (single block) ----------------
__global__ void build_lists_kernel() {
    __shared__ int cnt[NEXP], off[NEXP + 1], fill[NEXP];
    int tid = threadIdx.x;
    if (tid < NEXP) cnt[tid] = 0;
    __syncthreads();
    for (int i = tid; i < 2 * T_TOK; i += blockDim.x) atomicAdd(&cnt[g_texp[i]], 1);
    __syncthreads();
    if (tid == 0) {
        int o = 0;
        for (int e = 0; e < NEXP; e++) { off[e] = o; o += ((cnt[e] + MTILE - 1) / MTILE) * MTILE; }
        off[NEXP] = o;
    }
    __syncthreads();
    if (tid < NEXP)  fill[tid] = 0;
    if (tid <= NEXP) g_off[tid] = off[tid];
    for (int i = tid; i < ROWCAP; i += blockDim.x) g_rows[i] = -1;
    __syncthreads();
    for (int i = tid; i < 2 * T_TOK; i += blockDim.x) {
        int e = g_texp[i];
        int p = atomicAdd(&fill[e], 1);
        g_rows[off[e] + p] = (i >> 1) | ((i & 1) << 16);
    }
}

__device__ __forceinline__ int find_expert(int row0) {
    int e = 0;
#pragma unroll
    for (int q = 0; q < NEXP; q++)
        if (row0 >= g_off[q + 1]) e = q + 1;
    return e;
}

// ---------------- 3) GEMM1: h = silu(X@w1^T) * (X@w3^T), gathered rows ----------------
__global__ __launch_bounds__(256) void gemm1_kernel(const float* __restrict__ x,
                                                    const float* __restrict__ w1,
                                                    const float* __restrict__ w3) {
    __shared__ float As[BK][64];
    __shared__ float Bs1[BK][64];
    __shared__ float Bs3[BK][64];
    __shared__ int stok[64];

    int tid  = threadIdx.x;
    int row0 = blockIdx.y * MTILE;
    int n0   = blockIdx.x * 64;
    if (row0 >= g_off[NEXP]) return;
    int e = find_expert(row0);

    if (tid < 64) stok[tid] = g_rows[row0 + tid];
    __syncthreads();

    const float* B1g = w1 + (size_t)e * IDIM * HDIM;
    const float* B3g = w3 + (size_t)e * IDIM * HDIM;

    int ty = tid >> 4, tx = tid & 15;
    unsigned long long acc1[4][2], acc3[4][2];
#pragma unroll
    for (int i = 0; i < 4; i++) { acc1[i][0]=0ull; acc1[i][1]=0ull; acc3[i][0]=0ull; acc3[i][1]=0ull; }

    for (int k0 = 0; k0 < HDIM; k0 += BK) {
#pragma unroll
        for (int p = 0; p < 2; p++) {          // A tile 64x32 (gathered, transposed)
            int idx = tid + p * 256;
            int m = idx >> 3, kq = (idx & 7) << 2;
            int r = stok[m];
            float4 v = make_float4(0.f, 0.f, 0.f, 0.f);
            if (r >= 0) {
                int tok = r & 0xFFFF;
                v = *(const float4*)&x[(size_t)tok * HDIM + k0 + kq];
            }
            As[kq + 0][m] = v.x; As[kq + 1][m] = v.y; As[kq + 2][m] = v.z; As[kq + 3][m] = v.w;
        }
#pragma unroll
        for (int p = 0; p < 2; p++) {          // B1/B3 tiles 64x32 (transposed)
            int idx = tid + p * 256;
            int n = idx >> 3, kq = (idx & 7) << 2;
            float4 v1 = *(const float4*)&B1g[(size_t)(n0 + n) * HDIM + k0 + kq];
            float4 v3 = *(const float4*)&B3g[(size_t)(n0 + n) * HDIM + k0 + kq];
            Bs1[kq + 0][n] = v1.x; Bs1[kq + 1][n] = v1.y; Bs1[kq + 2][n] = v1.z; Bs1[kq + 3][n] = v1.w;
            Bs3[kq + 0][n] = v3.x; Bs3[kq + 1][n] = v3.y; Bs3[kq + 2][n] = v3.z; Bs3[kq + 3][n] = v3.w;
        }
        __syncthreads();
#pragma unroll 8
        for (int kk = 0; kk < BK; kk++) {
            float4 a4 = *(const float4*)&As[kk][ty * 4];
            unsigned long long ap0 = f2pack(a4.x, a4.x);
            unsigned long long ap1 = f2pack(a4.y, a4.y);
            unsigned long long ap2 = f2pack(a4.z, a4.z);
            unsigned long long ap3 = f2pack(a4.w, a4.w);
            ulonglong2 b1 = *(const ulonglong2*)&Bs1[kk][tx * 4];
            ulonglong2 b3 = *(const ulonglong2*)&Bs3[kk][tx * 4];
            acc1[0][0]=f2fma(ap0,b1.x,acc1[0][0]); acc1[0][1]=f2fma(ap0,b1.y,acc1[0][1]);
            acc3[0][0]=f2fma(ap0,b3.x,acc3[0][0]); acc3[0][1]=f2fma(ap0,b3.y,acc3[0][1]);
            acc1[1][0]=f2fma(ap1,b1.x,acc1[1][0]); acc1[1][1]=f2fma(ap1,b1.y,acc1[1][1]);
            acc3[1][0]=f2fma(ap1,b3.x,acc3[1][0]); acc3[1][1]=f2fma(ap1,b3.y,acc3[1][1]);
            acc1[2][0]=f2fma(ap2,b1.x,acc1[2][0]); acc1[2][1]=f2fma(ap2,b1.y,acc1[2][1]);
            acc3[2][0]=f2fma(ap2,b3.x,acc3[2][0]); acc3[2][1]=f2fma(ap2,b3.y,acc3[2][1]);
            acc1[3][0]=f2fma(ap3,b1.x,acc1[3][0]); acc1[3][1]=f2fma(ap3,b1.y,acc1[3][1]);
            acc3[3][0]=f2fma(ap3,b3.x,acc3[3][0]); acc3[3][1]=f2fma(ap3,b3.y,acc3[3][1]);
        }
        __syncthreads();
    }
    // epilogue: silu(c1) * c3  (pad rows have c1=c3=0 -> store 0, keeps hbuf clean)
#pragma unroll
    for (int i = 0; i < 4; i++) {
        float c1[4], c3[4];
        f2unpack(acc1[i][0], c1[0], c1[1]); f2unpack(acc1[i][1], c1[2], c1[3]);
        f2unpack(acc3[i][0], c3[0], c3[1]); f2unpack(acc3[i][1], c3[2], c3[3]);
        float4 hv;
        float* hp = (float*)&hv;
#pragma unroll
        for (int j = 0; j < 4; j++) {
            float s = c1[j] / (1.f + expf(-c1[j]));
            hp[j] = s * c3[j];
        }
        int m = ty * 4 + i;
        *(float4*)&g_hbuf[(size_t)(row0 + m) * IDIM + n0 + tx * 4] = hv;
    }
}

// ---------------- 4) GEMM2: out_pair[slot][tok] = w_tok * (h @ w2^T) ----------------
__global__ __launch_bounds__(256) void gemm2_kernel(const float* __restrict__ w2) {
    __shared__ float As[BK][64];
    __shared__ float Bs[BK][128];
    __shared__ int stok[64];

    int tid  = threadIdx.x;
    int row0 = blockIdx.y * MTILE;
    int n0   = blockIdx.x * 128;
    if (row0 >= g_off[NEXP]) return;
    int e = find_expert(row0);

    if (tid < 64) stok[tid] = g_rows[row0 + tid];

    const float* Bg = w2 + (size_t)e * HDIM * IDIM;
    int ty = tid >> 4, tx = tid & 15;
    unsigned long long acc[4][4];
#pragma unroll
    for (int i = 0; i < 4; i++)
#pragma unroll
        for (int j = 0; j < 4; j++) acc[i][j] = 0ull;

    for (int k0 = 0; k0 < IDIM; k0 += BK) {
#pragma unroll
        for (int p = 0; p < 2; p++) {          // A tile from hbuf (no gather)
            int idx = tid + p * 256;
            int m = idx >> 3, kq = (idx & 7) << 2;
            float4 v = *(const float4*)&g_hbuf[(size_t)(row0 + m) * IDIM + k0 + kq];
            As[kq + 0][m] = v.x; As[kq + 1][m] = v.y; As[kq + 2][m] = v.z; As[kq + 3][m] = v.w;
        }
#pragma unroll
        for (int p = 0; p < 4; p++) {          // B tile 128x32
            int idx = tid + p * 256;
            int n = idx >> 3, kq = (idx & 7) << 2;
            float4 v = *(const float4*)&Bg[(size_t)(n0 + n) * IDIM + k0 + kq];
            Bs[kq + 0][n] = v.x; Bs[kq + 1][n] = v.y; Bs[kq + 2][n] = v.z; Bs[kq + 3][n] = v.w;
        }
        __syncthreads();
#pragma unroll 8
        for (int kk = 0; kk < BK; kk++) {
            float4 a4 = *(const float4*)&As[kk][ty * 4];
            unsigned long long ap0 = f2pack(a4.x, a4.x);
            unsigned long long ap1 = f2pack(a4.y, a4.y);
            unsigned long long ap2 = f2pack(a4.z, a4.z);
            unsigned long long ap3 = f2pack(a4.w, a4.w);
            ulonglong2 bA = *(const ulonglong2*)&Bs[kk][tx * 8];
            ulonglong2 bB = *(const ulonglong2*)&Bs[kk][tx * 8 + 4];
            acc[0][0]=f2fma(ap0,bA.x,acc[0][0]); acc[0][1]=f2fma(ap0,bA.y,acc[0][1]);
            acc[0][2]=f2fma(ap0,bB.x,acc[0][2]); acc[0][3]=f2fma(ap0,bB.y,acc[0][3]);
            acc[1][0]=f2fma(ap1,bA.x,acc[1][0]); acc[1][1]=f2fma(ap1,bA.y,acc[1][1]);
            acc[1][2]=f2fma(ap1,bB.x,acc[1][2]); acc[1][3]=f2fma(ap1,bB.y,acc[1][3]);
            acc[2][0]=f2fma(ap2,bA.x,acc[2][0]); acc[2][1]=f2fma(ap2,bA.y,acc[2][1]);
            acc[2][2]=f2fma(ap2,bB.x,acc[2][2]); acc[2][3]=f2fma(ap2,bB.y,acc[2][3]);
            acc[3][0]=f2fma(ap3,bA.x,acc[3][0]); acc[3][1]=f2fma(ap3,bA.y,acc[3][1]);
            acc[3][2]=f2fma(ap3,bB.x,acc[3][2]); acc[3][3]=f2fma(ap3,bB.y,acc[3][3]);
        }
        __syncthreads();
    }
#pragma unroll
    for (int i = 0; i < 4; i++) {
        int r = stok[ty * 4 + i];
        if (r < 0) continue;                    // padding row
        int tok = r & 0xFFFF, slot = (r >> 16) & 1;
        float w = g_topw[tok * 2 + slot];
        float c[8];
        f2unpack(acc[i][0], c[0], c[1]); f2unpack(acc[i][1], c[2], c[3]);
        f2unpack(acc[i][2], c[4], c[5]); f2unpack(acc[i][3], c[6], c[7]);
        float4 o0 = make_float4(c[0]*w, c[1]*w, c[2]*w, c[3]*w);
        float4 o1 = make_float4(c[4]*w, c[5]*w, c[6]*w, c[7]*w);
        *(float4*)&g_outpair[slot][tok][n0 + tx * 8]     = o0;
        *(float4*)&g_outpair[slot][tok][n0 + tx * 8 + 4] = o1;
    }
}

// ---------------- 5) combine: out = slot0 + slot1 ----------------
__global__ void combine_kernel(float* __restrict__ out) {
    size_t i = (size_t)blockIdx.x * blockDim.x + threadIdx.x;
    const float4* p0 = (const float4*)&g_outpair[0][0][0];
    const float4* p1 = (const float4*)&g_outpair[1][0][0];
    float4 a = p0[i], b = p1[i];
    ((float4*)out)[i] = make_float4(a.x + b.x, a.y + b.y, a.z + b.z, a.w + b.w);
}

extern "C" void kernel_launch(void* const* d_in, const int* in_sizes, int n_in,
                              void* d_out, int out_size) {
    const float* x  = (const float*)d_in[0];
    const float* gw = (const float*)d_in[1];
    const float* gb = (const float*)d_in[2];
    const float* w1 = (const float*)d_in[3];
    const float* w2 = (const float*)d_in[4];
    const float* w3 = (const float*)d_in[5];
    float* out = (float*)d_out;

    router_kernel<<<T_TOK / 8, 256>>>(x, gw, gb);
    build_lists_kernel<<<1, 1024>>>();
    dim3 g1(IDIM / 64, ROWCAP / MTILE);   // (56, 264)
    gemm1_kernel<<<g1, 256>>>(x, w1, w3);
    dim3 g2(HDIM / 128, ROWCAP / MTILE);  // (8, 264)
    gemm2_kernel<<<g2, 256>>>(w2);
    combine_kernel<<<(T_TOK * HDIM / 4) / 256, 256>>>(out);
}